// round 2
// baseline (speedup 1.0000x reference)
#include <cuda_runtime.h>
#include <cuda_bf16.h>
#include <math.h>

// ---------------------------------------------------------------------------
// Problem constants
// ---------------------------------------------------------------------------
#define L_SEQ   2516          // 16 + 25*100
#define C_DIM   128
#define HEADS_N 8
#define DH      16
#define MLP_DIM 512
#define N_IMG   100           // 25 support + 75 query
#define HW      100           // 10x10
#define T_CH    32
#define KSPLIT  8
#define KSPAN   315           // ceil(2516/8)

// ---------------------------------------------------------------------------
// Scratch (device globals; no allocation allowed)
// ---------------------------------------------------------------------------
__device__ float g_X   [L_SEQ * C_DIM];
__device__ float g_H   [L_SEQ * C_DIM];
__device__ float g_QKV [L_SEQ * 3 * C_DIM];
__device__ float g_O   [L_SEQ * C_DIM];
__device__ float g_G   [L_SEQ * MLP_DIM];
__device__ float g_PART[KSPLIT * HEADS_N * L_SEQ * DH];
__device__ float g_ML  [KSPLIT * HEADS_N * L_SEQ * 2];
__device__ float g_FUSED[N_IMG * C_DIM * HW];
__device__ float g_LNT  [N_IMG * C_DIM * HW];
__device__ float g_T1   [N_IMG * T_CH * HW];
__device__ float g_T2   [N_IMG * T_CH * HW];

// ---------------------------------------------------------------------------
// build X = concat(task_descriptor, support permuted)
// ---------------------------------------------------------------------------
__global__ void build_x_k(const float* __restrict__ task,
                          const float* __restrict__ support,
                          float* __restrict__ X)
{
    int i = blockIdx.x * blockDim.x + threadIdx.x;
    if (i >= L_SEQ * C_DIM) return;
    int r = i >> 7;          // /128
    int c = i & 127;
    if (r < 16) {
        X[i] = task[r * C_DIM + c];
    } else {
        int rr = r - 16;
        int b = rr / HW, p = rr % HW;
        X[i] = support[b * C_DIM * HW + c * HW + p];
    }
}

// ---------------------------------------------------------------------------
// Row LayerNorm over last dim (128). One block (128 threads) per row.
// ---------------------------------------------------------------------------
__global__ void ln_rows_k(const float* __restrict__ X, const float* __restrict__ g,
                          const float* __restrict__ b, float* __restrict__ H, float eps)
{
    int r = blockIdx.x, t = threadIdx.x;
    float v = X[r * C_DIM + t];
    float s = v;
#pragma unroll
    for (int o = 16; o > 0; o >>= 1) s += __shfl_xor_sync(0xFFFFFFFFu, s, o);
    __shared__ float ws[4], ws2[4];
    int w = t >> 5, lane = t & 31;
    if (lane == 0) ws[w] = s;
    __syncthreads();
    float mean = (ws[0] + ws[1] + ws[2] + ws[3]) * (1.0f / 128.0f);
    float d = v - mean;
    float s2 = d * d;
#pragma unroll
    for (int o = 16; o > 0; o >>= 1) s2 += __shfl_xor_sync(0xFFFFFFFFu, s2, o);
    if (lane == 0) ws2[w] = s2;
    __syncthreads();
    float var = (ws2[0] + ws2[1] + ws2[2] + ws2[3]) * (1.0f / 128.0f);
    H[r * C_DIM + t] = d * rsqrtf(var + eps) * g[t] + b[t];
}

// ---------------------------------------------------------------------------
// Tiled GEMM  C[M,N] = A[M,K] @ B[K,N]  (+ epilogue)
// epi: 0 = +bias ; 1 = +bias+res ; 2 = gelu(+bias)
// BM=128, BN=64, BK=16, 256 threads, 8x4 per thread. K%16==0, N%64==0.
// ---------------------------------------------------------------------------
__global__ void gemm_epi_k(const float* __restrict__ A, const float* __restrict__ B,
                           const float* __restrict__ bias, const float* __restrict__ res,
                           float* __restrict__ C, int M, int N, int K, int epi)
{
    __shared__ __align__(16) float As[128][16];
    __shared__ __align__(16) float Bs[16][64];
    int bm = blockIdx.y * 128, bn = blockIdx.x * 64;
    int tid = threadIdx.x;
    int tx = tid & 15, ty = tid >> 4;     // tx: 16 col-groups of 4, ty: 16 row-groups of 8
    float acc[8][4];
#pragma unroll
    for (int i = 0; i < 8; i++)
#pragma unroll
        for (int j = 0; j < 4; j++) acc[i][j] = 0.0f;

    // A-load: 128x16 floats = 512 float4; 256 threads -> 2 float4 each
    int f0 = tid * 2;
    int ar0 = f0 >> 2, ac0 = (f0 & 3) * 4;
    int f1 = f0 + 1;
    int ar1 = f1 >> 2, ac1 = (f1 & 3) * 4;
    // B-load: 16x64 floats = 256 float4; one each
    int brow = tid >> 4, bcol = (tid & 15) * 4;

    for (int k0 = 0; k0 < K; k0 += 16) {
        float4 av0 = make_float4(0.f, 0.f, 0.f, 0.f);
        float4 av1 = make_float4(0.f, 0.f, 0.f, 0.f);
        if (bm + ar0 < M) av0 = *(const float4*)&A[(size_t)(bm + ar0) * K + k0 + ac0];
        if (bm + ar1 < M) av1 = *(const float4*)&A[(size_t)(bm + ar1) * K + k0 + ac1];
        *(float4*)&As[ar0][ac0] = av0;
        *(float4*)&As[ar1][ac1] = av1;
        float4 bv = *(const float4*)&B[(size_t)(k0 + brow) * N + bn + bcol];
        *(float4*)&Bs[brow][bcol] = bv;
        __syncthreads();
#pragma unroll
        for (int k = 0; k < 16; k++) {
            float4 b4 = *(const float4*)&Bs[k][tx * 4];
            float a[8];
#pragma unroll
            for (int i = 0; i < 8; i++) a[i] = As[ty * 8 + i][k];
#pragma unroll
            for (int i = 0; i < 8; i++) {
                acc[i][0] += a[i] * b4.x;
                acc[i][1] += a[i] * b4.y;
                acc[i][2] += a[i] * b4.z;
                acc[i][3] += a[i] * b4.w;
            }
        }
        __syncthreads();
    }
#pragma unroll
    for (int i = 0; i < 8; i++) {
        int r = bm + ty * 8 + i;
        if (r >= M) continue;
#pragma unroll
        for (int j = 0; j < 4; j++) {
            int cidx = bn + tx * 4 + j;
            float v = acc[i][j] + bias[cidx];
            if (epi == 1) v += res[(size_t)r * N + cidx];
            else if (epi == 2) v = 0.5f * v * (1.0f + erff(v * 0.70710678118654752f));
            C[(size_t)r * N + cidx] = v;
        }
    }
}

// ---------------------------------------------------------------------------
// Flash-style attention, split over keys (KSPLIT). One thread per query.
// grid (qtiles=20, heads=8, splits=8), block 128. 2 keys / iteration.
// ---------------------------------------------------------------------------
__global__ void attn_partial_k(const float* __restrict__ QKV,
                               float* __restrict__ PART, float* __restrict__ ML)
{
    int h  = blockIdx.y;
    int sp = blockIdx.z;
    int q  = blockIdx.x * 128 + threadIdx.x;
    int k0 = sp * KSPAN;
    int k1 = min(L_SEQ, k0 + KSPAN);

    __shared__ __align__(16) float4 Ks[64][4];
    __shared__ __align__(16) float4 Vs[64][4];

    bool act = q < L_SEQ;
    float4 qv[4];
    if (act) {
#pragma unroll
        for (int u = 0; u < 4; u++)
            qv[u] = *(const float4*)&QKV[(size_t)q * 384 + h * 16 + 4 * u];
    }
    float m = -INFINITY, l = 0.0f;
    float4 acc[4];
#pragma unroll
    for (int u = 0; u < 4; u++) acc[u] = make_float4(0.f, 0.f, 0.f, 0.f);

    for (int kc = k0; kc < k1; kc += 64) {
        int n = min(64, k1 - kc);
        // stage K/V tiles as float4
        for (int idx = threadIdx.x; idx < n * 4; idx += 128) {
            int row = idx >> 2, d4 = idx & 3;
            Ks[row][d4] = *(const float4*)&QKV[(size_t)(kc + row) * 384 + 128 + h * 16 + 4 * d4];
            Vs[row][d4] = *(const float4*)&QKV[(size_t)(kc + row) * 384 + 256 + h * 16 + 4 * d4];
        }
        __syncthreads();
        if (act) {
            int j = 0;
            for (; j + 2 <= n; j += 2) {
                float sa0, sa1, sa2, sa3, sb0, sb1, sb2, sb3;
                {
                    float4 k0a = Ks[j][0], k1a = Ks[j][1], k2a = Ks[j][2], k3a = Ks[j][3];
                    float4 k0b = Ks[j+1][0], k1b = Ks[j+1][1], k2b = Ks[j+1][2], k3b = Ks[j+1][3];
                    sa0 = qv[0].x*k0a.x + qv[0].y*k0a.y + qv[0].z*k0a.z + qv[0].w*k0a.w;
                    sa1 = qv[1].x*k1a.x + qv[1].y*k1a.y + qv[1].z*k1a.z + qv[1].w*k1a.w;
                    sa2 = qv[2].x*k2a.x + qv[2].y*k2a.y + qv[2].z*k2a.z + qv[2].w*k2a.w;
                    sa3 = qv[3].x*k3a.x + qv[3].y*k3a.y + qv[3].z*k3a.z + qv[3].w*k3a.w;
                    sb0 = qv[0].x*k0b.x + qv[0].y*k0b.y + qv[0].z*k0b.z + qv[0].w*k0b.w;
                    sb1 = qv[1].x*k1b.x + qv[1].y*k1b.y + qv[1].z*k1b.z + qv[1].w*k1b.w;
                    sb2 = qv[2].x*k2b.x + qv[2].y*k2b.y + qv[2].z*k2b.z + qv[2].w*k2b.w;
                    sb3 = qv[3].x*k3b.x + qv[3].y*k3b.y + qv[3].z*k3b.z + qv[3].w*k3b.w;
                }
                float sa = ((sa0 + sa1) + (sa2 + sa3)) * 0.25f;
                float sb = ((sb0 + sb1) + (sb2 + sb3)) * 0.25f;
                float mp = fmaxf(sa, sb);
                if (mp > m) {
                    float corr = __expf(m - mp);
                    l *= corr;
#pragma unroll
                    for (int u = 0; u < 4; u++) {
                        acc[u].x *= corr; acc[u].y *= corr; acc[u].z *= corr; acc[u].w *= corr;
                    }
                    m = mp;
                }
                float pa = __expf(sa - m);
                float pb = __expf(sb - m);
                l += pa + pb;
#pragma unroll
                for (int u = 0; u < 4; u++) {
                    float4 va = Vs[j][u];
                    float4 vb = Vs[j+1][u];
                    acc[u].x += pa * va.x + pb * vb.x;
                    acc[u].y += pa * va.y + pb * vb.y;
                    acc[u].z += pa * va.z + pb * vb.z;
                    acc[u].w += pa * va.w + pb * vb.w;
                }
            }
            if (j < n) {  // odd tail key
                float s0, s1, s2, s3;
                float4 ka = Ks[j][0], kb = Ks[j][1], kc2 = Ks[j][2], kd = Ks[j][3];
                s0 = qv[0].x*ka.x + qv[0].y*ka.y + qv[0].z*ka.z + qv[0].w*ka.w;
                s1 = qv[1].x*kb.x + qv[1].y*kb.y + qv[1].z*kb.z + qv[1].w*kb.w;
                s2 = qv[2].x*kc2.x + qv[2].y*kc2.y + qv[2].z*kc2.z + qv[2].w*kc2.w;
                s3 = qv[3].x*kd.x + qv[3].y*kd.y + qv[3].z*kd.z + qv[3].w*kd.w;
                float s = ((s0 + s1) + (s2 + s3)) * 0.25f;
                if (s > m) {
                    float corr = __expf(m - s);
                    l *= corr;
#pragma unroll
                    for (int u = 0; u < 4; u++) {
                        acc[u].x *= corr; acc[u].y *= corr; acc[u].z *= corr; acc[u].w *= corr;
                    }
                    m = s;
                }
                float p = __expf(s - m);
                l += p;
#pragma unroll
                for (int u = 0; u < 4; u++) {
                    float4 vv = Vs[j][u];
                    acc[u].x += p * vv.x; acc[u].y += p * vv.y;
                    acc[u].z += p * vv.z; acc[u].w += p * vv.w;
                }
            }
        }
        __syncthreads();
    }
    if (act) {
        size_t idx = ((size_t)(sp * HEADS_N + h) * L_SEQ + q);
        float4* pb = (float4*)&PART[idx * 16];
#pragma unroll
        for (int u = 0; u < 4; u++) pb[u] = acc[u];
        ML[idx * 2 + 0] = m;
        ML[idx * 2 + 1] = l;
    }
}

__global__ void attn_merge_k(const float* __restrict__ PART, const float* __restrict__ ML,
                             float* __restrict__ O)
{
    int t = blockIdx.x * blockDim.x + threadIdx.x;
    if (t >= HEADS_N * L_SEQ) return;
    int h = t / L_SEQ, q = t % L_SEQ;
    float mm[KSPLIT], ll[KSPLIT];
    float M = -INFINITY;
#pragma unroll
    for (int sp = 0; sp < KSPLIT; sp++) {
        size_t idx = ((size_t)(sp * HEADS_N + h) * L_SEQ + q);
        mm[sp] = ML[idx * 2 + 0];
        ll[sp] = ML[idx * 2 + 1];
        M = fmaxf(M, mm[sp]);
    }
    float wsum = 0.0f, w[KSPLIT];
#pragma unroll
    for (int sp = 0; sp < KSPLIT; sp++) {
        w[sp] = __expf(mm[sp] - M);
        wsum += ll[sp] * w[sp];
    }
    float inv = 1.0f / wsum;
    float o[DH];
#pragma unroll
    for (int d = 0; d < DH; d++) o[d] = 0.0f;
#pragma unroll
    for (int sp = 0; sp < KSPLIT; sp++) {
        size_t idx = ((size_t)(sp * HEADS_N + h) * L_SEQ + q);
        const float4* pb = (const float4*)&PART[idx * 16];
#pragma unroll
        for (int u = 0; u < 4; u++) {
            float4 v = pb[u];
            o[4*u+0] += v.x * w[sp];
            o[4*u+1] += v.y * w[sp];
            o[4*u+2] += v.z * w[sp];
            o[4*u+3] += v.w * w[sp];
        }
    }
#pragma unroll
    for (int d = 0; d < DH; d++)
        O[(size_t)q * C_DIM + h * DH + d] = o[d] * inv;
}

// ---------------------------------------------------------------------------
// region + map_fuse: one block per image, thread per pixel.
// ---------------------------------------------------------------------------
__global__ void region_fuse_k(const float* __restrict__ support, const float* __restrict__ query,
                              const float* __restrict__ X, float* __restrict__ F)
{
    int img = blockIdx.x;
    __shared__ float key[16 * C_DIM];
    for (int i = threadIdx.x; i < 16 * C_DIM; i += 128) key[i] = X[i];
    __syncthreads();
    const float* feat = (img < 25) ? support + (size_t)img * C_DIM * HW
                                   : query + (size_t)(img - 25) * C_DIM * HW;
    float* fb = F + (size_t)img * C_DIM * HW;
    int p = threadIdx.x;
    if (p < HW) {
        float dot[16];
#pragma unroll
        for (int m = 0; m < 16; m++) dot[m] = 0.0f;
        for (int c = 0; c < C_DIM; c++) {
            float f = feat[c * HW + p];
#pragma unroll
            for (int m = 0; m < 16; m++) dot[m] += key[m * C_DIM + c] * f;
        }
        float s = 0.0f;
#pragma unroll
        for (int m = 0; m < 16; m++)
            s += 1.0f / (1.0f + __expf(-dot[m] * (1.0f / 128.0f)));
        s = s * (1.0f / 16.0f) + 1.0f;
        for (int c = 0; c < C_DIM; c++)
            fb[c * HW + p] = feat[c * HW + p] * s;
    }
}

// ---------------------------------------------------------------------------
// channel LayerNorm: per (image, pixel) over 128 channels. eps 1e-6.
// ---------------------------------------------------------------------------
__global__ void ln_chan_k(const float* __restrict__ F, const float* __restrict__ g,
                          const float* __restrict__ b, float* __restrict__ Out)
{
    int img = blockIdx.x;
    int p = threadIdx.x;
    if (p >= HW) return;
    const float* fb = F + (size_t)img * C_DIM * HW;
    float s = 0.0f;
    for (int c = 0; c < C_DIM; c++) s += fb[c * HW + p];
    float mean = s * (1.0f / 128.0f);
    float v = 0.0f;
    for (int c = 0; c < C_DIM; c++) {
        float d = fb[c * HW + p] - mean;
        v += d * d;
    }
    v *= (1.0f / 128.0f);
    float rs = rsqrtf(v + 1e-6f);
    float* ob = Out + (size_t)img * C_DIM * HW;
    for (int c = 0; c < C_DIM; c++)
        ob[c * HW + p] = (fb[c * HW + p] - mean) * rs * g[c] + b[c];
}

// ---------------------------------------------------------------------------
// 3x3 conv, pad 1, 10x10, Cout=32. Block per image (256 thr).
// ---------------------------------------------------------------------------
__global__ void conv3x3_k(const float* __restrict__ in, const float* __restrict__ w,
                          float* __restrict__ out, int Cin, int do_relu)
{
    extern __shared__ float s_in[];  // Cin*144
    int img = blockIdx.x;
    int tid = threadIdx.x;
    const float* inb = in + (size_t)img * Cin * HW;
    for (int idx = tid; idx < Cin * 144; idx += 256) {
        int c = idx / 144, pos = idx % 144;
        int y = pos / 12 - 1, x = pos % 12 - 1;
        float v = 0.0f;
        if (y >= 0 && y < 10 && x >= 0 && x < 10) v = inb[c * HW + y * 10 + x];
        s_in[idx] = v;
    }
    __syncthreads();

    int oc = tid >> 3, lane = tid & 7;
    float acc[13];
    int base[13];
#pragma unroll
    for (int t = 0; t < 13; t++) {
        acc[t] = 0.0f;
        int p = lane + 8 * t;
        if (p > 99) p = 99;
        int y = p / 10, x = p % 10;
        base[t] = y * 12 + x;
    }
    const float* wb = w + (size_t)oc * Cin * 9;
    for (int c = 0; c < Cin; c++) {
        const float* sc = s_in + c * 144;
#pragma unroll
        for (int kk = 0; kk < 9; kk++) {
            float wv = wb[c * 9 + kk];
            int off = (kk / 3) * 12 + (kk % 3);
#pragma unroll
            for (int t = 0; t < 13; t++)
                acc[t] += sc[base[t] + off] * wv;
        }
    }
    float* ob = out + (size_t)img * T_CH * HW + oc * HW;
#pragma unroll
    for (int t = 0; t < 13; t++) {
        int p = lane + 8 * t;
        if (p < HW) {
            float v = acc[t];
            if (do_relu) v = fmaxf(v, 0.0f);
            ob[p] = v;
        }
    }
}

// ---------------------------------------------------------------------------
// Final: out[b][c][t] = (1/100) * sum_p sigmoid(T4[b][t][p]) * F[b][c][p]
// ---------------------------------------------------------------------------
__global__ void rfm_out_k(const float* __restrict__ T4, const float* __restrict__ F,
                          float* __restrict__ out)
{
    int img = blockIdx.x;
    __shared__ float sig[HW * T_CH];  // [p][t]
    int tid = threadIdx.x;
    for (int idx = tid; idx < T_CH * HW; idx += 256) {
        int t = idx / HW, p = idx % HW;
        float v = T4[(size_t)img * T_CH * HW + idx];
        sig[p * T_CH + t] = 1.0f / (1.0f + __expf(-v));
    }
    __syncthreads();
    float* ob = out + (size_t)img * 4096;
    const float* fb = F + (size_t)img * C_DIM * HW;
    for (int o = tid; o < C_DIM * T_CH; o += 256) {
        int c = o >> 5, t = o & 31;
        float s = 0.0f;
        for (int p = 0; p < HW; p++)
            s += fb[c * HW + p] * sig[p * T_CH + t];
        ob[c * T_CH + t] = s * (1.0f / 100.0f);
    }
}

// ---------------------------------------------------------------------------
// Host launcher
// ---------------------------------------------------------------------------
extern "C" void kernel_launch(void* const* d_in, const int* in_sizes, int n_in,
                              void* d_out, int out_size)
{
    const float* support = (const float*)d_in[0];
    const float* query   = (const float*)d_in[1];
    const float* task    = (const float*)d_in[2];
    const float* ln1_g   = (const float*)d_in[3];
    const float* ln1_b   = (const float*)d_in[4];
    const float* qkv_w   = (const float*)d_in[5];
    const float* qkv_b   = (const float*)d_in[6];
    const float* out_w   = (const float*)d_in[7];
    const float* out_b   = (const float*)d_in[8];
    const float* ln2_g   = (const float*)d_in[9];
    const float* ln2_b   = (const float*)d_in[10];
    const float* mlp_w1  = (const float*)d_in[11];
    const float* mlp_b1  = (const float*)d_in[12];
    const float* mlp_w2  = (const float*)d_in[13];
    const float* mlp_b2  = (const float*)d_in[14];
    const float* rln_g   = (const float*)d_in[15];
    const float* rln_b   = (const float*)d_in[16];
    const float* conv1   = (const float*)d_in[17];
    const float* conv2   = (const float*)d_in[18];
    const float* conv3   = (const float*)d_in[19];
    const float* conv4   = (const float*)d_in[20];

    float *X, *H, *QKV, *O, *G, *PART, *ML, *FUSED, *LNT, *T1, *T2;
    cudaGetSymbolAddress((void**)&X, g_X);
    cudaGetSymbolAddress((void**)&H, g_H);
    cudaGetSymbolAddress((void**)&QKV, g_QKV);
    cudaGetSymbolAddress((void**)&O, g_O);
    cudaGetSymbolAddress((void**)&G, g_G);
    cudaGetSymbolAddress((void**)&PART, g_PART);
    cudaGetSymbolAddress((void**)&ML, g_ML);
    cudaGetSymbolAddress((void**)&FUSED, g_FUSED);
    cudaGetSymbolAddress((void**)&LNT, g_LNT);
    cudaGetSymbolAddress((void**)&T1, g_T1);
    cudaGetSymbolAddress((void**)&T2, g_T2);

    cudaFuncSetAttribute(conv3x3_k, cudaFuncAttributeMaxDynamicSharedMemorySize,
                         C_DIM * 144 * sizeof(float));

    // Build sequence
    build_x_k<<<(L_SEQ * C_DIM + 255) / 256, 256>>>(task, support, X);

    // Transformer (2 layers)
    for (int i = 0; i < 2; i++) {
        ln_rows_k<<<L_SEQ, 128>>>(X, ln1_g + i * C_DIM, ln1_b + i * C_DIM, H, 1e-5f);
        gemm_epi_k<<<dim3(6, 20), 256>>>(H, qkv_w + (size_t)i * C_DIM * 384,
                                         qkv_b + i * 384, nullptr, QKV,
                                         L_SEQ, 384, C_DIM, 0);
        attn_partial_k<<<dim3(20, HEADS_N, KSPLIT), 128>>>(QKV, PART, ML);
        attn_merge_k<<<(HEADS_N * L_SEQ + 127) / 128, 128>>>(PART, ML, O);
        gemm_epi_k<<<dim3(2, 20), 256>>>(O, out_w + (size_t)i * C_DIM * C_DIM,
                                         out_b + i * C_DIM, X, X,
                                         L_SEQ, C_DIM, C_DIM, 1);
        ln_rows_k<<<L_SEQ, 128>>>(X, ln2_g + i * C_DIM, ln2_b + i * C_DIM, H, 1e-5f);
        gemm_epi_k<<<dim3(8, 20), 256>>>(H, mlp_w1 + (size_t)i * C_DIM * MLP_DIM,
                                         mlp_b1 + i * MLP_DIM, nullptr, G,
                                         L_SEQ, MLP_DIM, C_DIM, 2);
        gemm_epi_k<<<dim3(2, 20), 256>>>(G, mlp_w2 + (size_t)i * MLP_DIM * C_DIM,
                                         mlp_b2 + i * C_DIM, X, X,
                                         L_SEQ, C_DIM, MLP_DIM, 1);
    }

    // Region + fuse
    region_fuse_k<<<N_IMG, 128>>>(support, query, X, FUSED);
    ln_chan_k<<<N_IMG, 128>>>(FUSED, rln_g, rln_b, LNT);

    // RFM convs
    conv3x3_k<<<N_IMG, 256, C_DIM * 144 * sizeof(float)>>>(LNT, conv1, T1, C_DIM, 1);
    conv3x3_k<<<N_IMG, 256, T_CH * 144 * sizeof(float)>>>(T1, conv2, T2, T_CH, 1);
    conv3x3_k<<<N_IMG, 256, T_CH * 144 * sizeof(float)>>>(T2, conv3, T1, T_CH, 1);
    conv3x3_k<<<N_IMG, 256, T_CH * 144 * sizeof(float)>>>(T1, conv4, T2, T_CH, 0);

    // Weighted pooling -> output
    rfm_out_k<<<N_IMG, 256>>>(T2, FUSED, (float*)d_out);
}

// round 3
// speedup vs baseline: 1.1391x; 1.1391x over previous
#include <cuda_runtime.h>
#include <cuda_bf16.h>
#include <math.h>

// ---------------------------------------------------------------------------
// Problem constants
// ---------------------------------------------------------------------------
#define L_SEQ   2516          // 16 + 25*100
#define C_DIM   128
#define HEADS_N 8
#define DH      16
#define MLP_DIM 512
#define N_IMG   100           // 25 support + 75 query
#define HW      100           // 10x10
#define T_CH    32
#define KSPLIT  7
#define KSPAN   360           // ceil(2516/7)
#define KSPLIT_MAX 8

// ---------------------------------------------------------------------------
// Scratch (device globals; no allocation allowed)
// ---------------------------------------------------------------------------
__device__ float g_X   [L_SEQ * C_DIM];
__device__ float g_H   [L_SEQ * C_DIM];
__device__ float g_QKV [L_SEQ * 3 * C_DIM];
__device__ float g_O   [L_SEQ * C_DIM];
__device__ float g_G   [L_SEQ * MLP_DIM];
__device__ float g_PART[KSPLIT_MAX * HEADS_N * L_SEQ * DH];
__device__ float g_ML  [KSPLIT_MAX * HEADS_N * L_SEQ * 2];
__device__ float g_FUSED[N_IMG * C_DIM * HW];
__device__ float g_LNT  [N_IMG * C_DIM * HW];
__device__ float g_T1   [N_IMG * T_CH * HW];
__device__ float g_T2   [N_IMG * T_CH * HW];

__device__ __forceinline__ float dot4(float4 a, float4 b) {
    return a.x * b.x + a.y * b.y + a.z * b.z + a.w * b.w;
}

// ---------------------------------------------------------------------------
// build X = concat(task_descriptor, support permuted)
// ---------------------------------------------------------------------------
__global__ void build_x_k(const float* __restrict__ task,
                          const float* __restrict__ support,
                          float* __restrict__ X)
{
    int i = blockIdx.x * blockDim.x + threadIdx.x;
    if (i >= L_SEQ * C_DIM) return;
    int r = i >> 7;          // /128
    int c = i & 127;
    if (r < 16) {
        X[i] = task[r * C_DIM + c];
    } else {
        int rr = r - 16;
        int b = rr / HW, p = rr % HW;
        X[i] = support[b * C_DIM * HW + c * HW + p];
    }
}

// ---------------------------------------------------------------------------
// Row LayerNorm over last dim (128). One block (128 threads) per row.
// ---------------------------------------------------------------------------
__global__ void ln_rows_k(const float* __restrict__ X, const float* __restrict__ g,
                          const float* __restrict__ b, float* __restrict__ H, float eps)
{
    int r = blockIdx.x, t = threadIdx.x;
    float v = X[r * C_DIM + t];
    float s = v;
#pragma unroll
    for (int o = 16; o > 0; o >>= 1) s += __shfl_xor_sync(0xFFFFFFFFu, s, o);
    __shared__ float ws[4], ws2[4];
    int w = t >> 5, lane = t & 31;
    if (lane == 0) ws[w] = s;
    __syncthreads();
    float mean = (ws[0] + ws[1] + ws[2] + ws[3]) * (1.0f / 128.0f);
    float d = v - mean;
    float s2 = d * d;
#pragma unroll
    for (int o = 16; o > 0; o >>= 1) s2 += __shfl_xor_sync(0xFFFFFFFFu, s2, o);
    if (lane == 0) ws2[w] = s2;
    __syncthreads();
    float var = (ws2[0] + ws2[1] + ws2[2] + ws2[3]) * (1.0f / 128.0f);
    H[r * C_DIM + t] = d * rsqrtf(var + eps) * g[t] + b[t];
}

// ---------------------------------------------------------------------------
// Tiled GEMM  C[M,N] = A[M,K] @ B[K,N]  (+ epilogue)
// epi: 0 = +bias ; 1 = +bias+res ; 2 = gelu(+bias)
// BM=BN=64, BK=16, 256 threads, 4x4 per thread. A staged transposed in smem.
// ---------------------------------------------------------------------------
__global__ void gemm_epi_k(const float* __restrict__ A, const float* __restrict__ B,
                           const float* __restrict__ bias, const float* __restrict__ res,
                           float* __restrict__ C, int M, int N, int K, int epi)
{
    __shared__ __align__(16) float As[16][68];   // [k][row], padded
    __shared__ __align__(16) float Bs[16][64];
    int bm = blockIdx.y * 64, bn = blockIdx.x * 64;
    int tid = threadIdx.x;
    int tx = tid & 15, ty = tid >> 4;
    float acc[4][4];
#pragma unroll
    for (int i = 0; i < 4; i++)
#pragma unroll
        for (int j = 0; j < 4; j++) acc[i][j] = 0.0f;

    int ar = tid >> 2, ac = (tid & 3) * 4;       // A loader: row 0..63, k-offset
    int brow = tid >> 4, bcol = (tid & 15) * 4;  // B loader

    for (int k0 = 0; k0 < K; k0 += 16) {
        float4 av = make_float4(0.f, 0.f, 0.f, 0.f);
        if (bm + ar < M)
            av = *(const float4*)&A[(size_t)(bm + ar) * K + k0 + ac];
        As[ac + 0][ar] = av.x;
        As[ac + 1][ar] = av.y;
        As[ac + 2][ar] = av.z;
        As[ac + 3][ar] = av.w;
        float4 bv = *(const float4*)&B[(size_t)(k0 + brow) * N + bn + bcol];
        *(float4*)&Bs[brow][bcol] = bv;
        __syncthreads();
#pragma unroll
        for (int k = 0; k < 16; k++) {
            float4 a4 = *(const float4*)&As[k][ty * 4];
            float4 b4 = *(const float4*)&Bs[k][tx * 4];
            acc[0][0] += a4.x * b4.x; acc[0][1] += a4.x * b4.y; acc[0][2] += a4.x * b4.z; acc[0][3] += a4.x * b4.w;
            acc[1][0] += a4.y * b4.x; acc[1][1] += a4.y * b4.y; acc[1][2] += a4.y * b4.z; acc[1][3] += a4.y * b4.w;
            acc[2][0] += a4.z * b4.x; acc[2][1] += a4.z * b4.y; acc[2][2] += a4.z * b4.z; acc[2][3] += a4.z * b4.w;
            acc[3][0] += a4.w * b4.x; acc[3][1] += a4.w * b4.y; acc[3][2] += a4.w * b4.z; acc[3][3] += a4.w * b4.w;
        }
        __syncthreads();
    }
#pragma unroll
    for (int i = 0; i < 4; i++) {
        int r = bm + ty * 4 + i;
        if (r >= M) continue;
#pragma unroll
        for (int j = 0; j < 4; j++) {
            int cidx = bn + tx * 4 + j;
            float v = acc[i][j] + bias[cidx];
            if (epi == 1) v += res[(size_t)r * N + cidx];
            else if (epi == 2) v = 0.5f * v * (1.0f + erff(v * 0.70710678118654752f));
            C[(size_t)r * N + cidx] = v;
        }
    }
}

// ---------------------------------------------------------------------------
// Flash-style attention, split over keys (KSPLIT). 2 queries/thread, 2 keys/iter.
// grid (ceil(2516/256)=10, heads=8, splits=7), block 128.
// ---------------------------------------------------------------------------
__global__ void __launch_bounds__(128)
attn_partial_k(const float* __restrict__ QKV,
               float* __restrict__ PART, float* __restrict__ ML)
{
    int h  = blockIdx.y;
    int sp = blockIdx.z;
    int tid = threadIdx.x;
    int q0 = blockIdx.x * 256 + tid;
    int q1 = q0 + 128;
    int k0 = sp * KSPAN;
    int k1 = min(L_SEQ, k0 + KSPAN);

    __shared__ __align__(16) float4 Ks[64][4];
    __shared__ __align__(16) float4 Vs[64][4];

    bool act0 = q0 < L_SEQ, act1 = q1 < L_SEQ;
    float4 qa[4], qb[4];
#pragma unroll
    for (int u = 0; u < 4; u++) {
        qa[u] = act0 ? *(const float4*)&QKV[(size_t)q0 * 384 + h * 16 + 4 * u]
                     : make_float4(0.f, 0.f, 0.f, 0.f);
        qb[u] = act1 ? *(const float4*)&QKV[(size_t)q1 * 384 + h * 16 + 4 * u]
                     : make_float4(0.f, 0.f, 0.f, 0.f);
    }
    float m0 = -INFINITY, l0 = 0.0f, m1 = -INFINITY, l1 = 0.0f;
    float4 A0[4], A1[4];
#pragma unroll
    for (int u = 0; u < 4; u++) {
        A0[u] = make_float4(0.f, 0.f, 0.f, 0.f);
        A1[u] = make_float4(0.f, 0.f, 0.f, 0.f);
    }

    for (int kc = k0; kc < k1; kc += 64) {
        int n = min(64, k1 - kc);
        for (int idx = tid; idx < n * 4; idx += 128) {
            int row = idx >> 2, d4 = idx & 3;
            Ks[row][d4] = *(const float4*)&QKV[(size_t)(kc + row) * 384 + 128 + h * 16 + 4 * d4];
            Vs[row][d4] = *(const float4*)&QKV[(size_t)(kc + row) * 384 + 256 + h * 16 + 4 * d4];
        }
        __syncthreads();
        int j = 0;
        for (; j + 2 <= n; j += 2) {
            float4 Ka0 = Ks[j][0],   Ka1 = Ks[j][1],   Ka2 = Ks[j][2],   Ka3 = Ks[j][3];
            float4 Kb0 = Ks[j+1][0], Kb1 = Ks[j+1][1], Kb2 = Ks[j+1][2], Kb3 = Ks[j+1][3];
            float s00 = ((dot4(qa[0], Ka0) + dot4(qa[1], Ka1)) + (dot4(qa[2], Ka2) + dot4(qa[3], Ka3))) * 0.25f;
            float s01 = ((dot4(qa[0], Kb0) + dot4(qa[1], Kb1)) + (dot4(qa[2], Kb2) + dot4(qa[3], Kb3))) * 0.25f;
            float s10 = ((dot4(qb[0], Ka0) + dot4(qb[1], Ka1)) + (dot4(qb[2], Ka2) + dot4(qb[3], Ka3))) * 0.25f;
            float s11 = ((dot4(qb[0], Kb0) + dot4(qb[1], Kb1)) + (dot4(qb[2], Kb2) + dot4(qb[3], Kb3))) * 0.25f;

            float mp0 = fmaxf(s00, s01);
            if (mp0 > m0) {
                float corr = __expf(m0 - mp0);
                l0 *= corr;
#pragma unroll
                for (int u = 0; u < 4; u++) {
                    A0[u].x *= corr; A0[u].y *= corr; A0[u].z *= corr; A0[u].w *= corr;
                }
                m0 = mp0;
            }
            float p00 = __expf(s00 - m0), p01 = __expf(s01 - m0);
            l0 += p00 + p01;

            float mp1 = fmaxf(s10, s11);
            if (mp1 > m1) {
                float corr = __expf(m1 - mp1);
                l1 *= corr;
#pragma unroll
                for (int u = 0; u < 4; u++) {
                    A1[u].x *= corr; A1[u].y *= corr; A1[u].z *= corr; A1[u].w *= corr;
                }
                m1 = mp1;
            }
            float p10 = __expf(s10 - m1), p11 = __expf(s11 - m1);
            l1 += p10 + p11;

#pragma unroll
            for (int u = 0; u < 4; u++) {
                float4 va = Vs[j][u];
                float4 vb = Vs[j+1][u];
                A0[u].x += p00 * va.x + p01 * vb.x;
                A0[u].y += p00 * va.y + p01 * vb.y;
                A0[u].z += p00 * va.z + p01 * vb.z;
                A0[u].w += p00 * va.w + p01 * vb.w;
                A1[u].x += p10 * va.x + p11 * vb.x;
                A1[u].y += p10 * va.y + p11 * vb.y;
                A1[u].z += p10 * va.z + p11 * vb.z;
                A1[u].w += p10 * va.w + p11 * vb.w;
            }
        }
        if (j < n) {   // tail key (n always even here, kept for safety)
            float4 Ka0 = Ks[j][0], Ka1 = Ks[j][1], Ka2 = Ks[j][2], Ka3 = Ks[j][3];
            float s0 = ((dot4(qa[0], Ka0) + dot4(qa[1], Ka1)) + (dot4(qa[2], Ka2) + dot4(qa[3], Ka3))) * 0.25f;
            float s1 = ((dot4(qb[0], Ka0) + dot4(qb[1], Ka1)) + (dot4(qb[2], Ka2) + dot4(qb[3], Ka3))) * 0.25f;
            if (s0 > m0) {
                float corr = __expf(m0 - s0);
                l0 *= corr;
#pragma unroll
                for (int u = 0; u < 4; u++) {
                    A0[u].x *= corr; A0[u].y *= corr; A0[u].z *= corr; A0[u].w *= corr;
                }
                m0 = s0;
            }
            float p0 = __expf(s0 - m0); l0 += p0;
            if (s1 > m1) {
                float corr = __expf(m1 - s1);
                l1 *= corr;
#pragma unroll
                for (int u = 0; u < 4; u++) {
                    A1[u].x *= corr; A1[u].y *= corr; A1[u].z *= corr; A1[u].w *= corr;
                }
                m1 = s1;
            }
            float p1 = __expf(s1 - m1); l1 += p1;
#pragma unroll
            for (int u = 0; u < 4; u++) {
                float4 va = Vs[j][u];
                A0[u].x += p0 * va.x; A0[u].y += p0 * va.y; A0[u].z += p0 * va.z; A0[u].w += p0 * va.w;
                A1[u].x += p1 * va.x; A1[u].y += p1 * va.y; A1[u].z += p1 * va.z; A1[u].w += p1 * va.w;
            }
        }
        __syncthreads();
    }
    if (act0) {
        size_t idx = ((size_t)(sp * HEADS_N + h) * L_SEQ + q0);
        float4* pb = (float4*)&PART[idx * 16];
#pragma unroll
        for (int u = 0; u < 4; u++) pb[u] = A0[u];
        ML[idx * 2 + 0] = m0;
        ML[idx * 2 + 1] = l0;
    }
    if (act1) {
        size_t idx = ((size_t)(sp * HEADS_N + h) * L_SEQ + q1);
        float4* pb = (float4*)&PART[idx * 16];
#pragma unroll
        for (int u = 0; u < 4; u++) pb[u] = A1[u];
        ML[idx * 2 + 0] = m1;
        ML[idx * 2 + 1] = l1;
    }
}

__global__ void attn_merge_k(const float* __restrict__ PART, const float* __restrict__ ML,
                             float* __restrict__ O)
{
    int t = blockIdx.x * blockDim.x + threadIdx.x;
    if (t >= HEADS_N * L_SEQ) return;
    int h = t / L_SEQ, q = t % L_SEQ;
    float mm[KSPLIT], ll[KSPLIT];
    float M = -INFINITY;
#pragma unroll
    for (int sp = 0; sp < KSPLIT; sp++) {
        size_t idx = ((size_t)(sp * HEADS_N + h) * L_SEQ + q);
        mm[sp] = ML[idx * 2 + 0];
        ll[sp] = ML[idx * 2 + 1];
        M = fmaxf(M, mm[sp]);
    }
    float wsum = 0.0f, w[KSPLIT];
#pragma unroll
    for (int sp = 0; sp < KSPLIT; sp++) {
        w[sp] = __expf(mm[sp] - M);
        wsum += ll[sp] * w[sp];
    }
    float inv = 1.0f / wsum;
    float o[DH];
#pragma unroll
    for (int d = 0; d < DH; d++) o[d] = 0.0f;
#pragma unroll
    for (int sp = 0; sp < KSPLIT; sp++) {
        size_t idx = ((size_t)(sp * HEADS_N + h) * L_SEQ + q);
        const float4* pb = (const float4*)&PART[idx * 16];
#pragma unroll
        for (int u = 0; u < 4; u++) {
            float4 v = pb[u];
            o[4*u+0] += v.x * w[sp];
            o[4*u+1] += v.y * w[sp];
            o[4*u+2] += v.z * w[sp];
            o[4*u+3] += v.w * w[sp];
        }
    }
#pragma unroll
    for (int d = 0; d < DH; d++)
        O[(size_t)q * C_DIM + h * DH + d] = o[d] * inv;
}

// ---------------------------------------------------------------------------
// region + map_fuse: one block per image, thread per pixel.
// ---------------------------------------------------------------------------
__global__ void region_fuse_k(const float* __restrict__ support, const float* __restrict__ query,
                              const float* __restrict__ X, float* __restrict__ F)
{
    int img = blockIdx.x;
    __shared__ float key[16 * C_DIM];
    for (int i = threadIdx.x; i < 16 * C_DIM; i += 128) key[i] = X[i];
    __syncthreads();
    const float* feat = (img < 25) ? support + (size_t)img * C_DIM * HW
                                   : query + (size_t)(img - 25) * C_DIM * HW;
    float* fb = F + (size_t)img * C_DIM * HW;
    int p = threadIdx.x;
    if (p < HW) {
        float dot[16];
#pragma unroll
        for (int m = 0; m < 16; m++) dot[m] = 0.0f;
        for (int c = 0; c < C_DIM; c++) {
            float f = feat[c * HW + p];
#pragma unroll
            for (int m = 0; m < 16; m++) dot[m] += key[m * C_DIM + c] * f;
        }
        float s = 0.0f;
#pragma unroll
        for (int m = 0; m < 16; m++)
            s += 1.0f / (1.0f + __expf(-dot[m] * (1.0f / 128.0f)));
        s = s * (1.0f / 16.0f) + 1.0f;
        for (int c = 0; c < C_DIM; c++)
            fb[c * HW + p] = feat[c * HW + p] * s;
    }
}

// ---------------------------------------------------------------------------
// channel LayerNorm: per (image, pixel) over 128 channels. eps 1e-6.
// ---------------------------------------------------------------------------
__global__ void ln_chan_k(const float* __restrict__ F, const float* __restrict__ g,
                          const float* __restrict__ b, float* __restrict__ Out)
{
    int img = blockIdx.x;
    int p = threadIdx.x;
    if (p >= HW) return;
    const float* fb = F + (size_t)img * C_DIM * HW;
    float s = 0.0f;
    for (int c = 0; c < C_DIM; c++) s += fb[c * HW + p];
    float mean = s * (1.0f / 128.0f);
    float v = 0.0f;
    for (int c = 0; c < C_DIM; c++) {
        float d = fb[c * HW + p] - mean;
        v += d * d;
    }
    v *= (1.0f / 128.0f);
    float rs = rsqrtf(v + 1e-6f);
    float* ob = Out + (size_t)img * C_DIM * HW;
    for (int c = 0; c < C_DIM; c++)
        ob[c * HW + p] = (fb[c * HW + p] - mean) * rs * g[c] + b[c];
}

// ---------------------------------------------------------------------------
// 3x3 conv, pad 1, 10x10, Cout=32. grid (image, oc-half), 256 threads.
// Each block: 16 oc x 16 lanes x 7 px.
// ---------------------------------------------------------------------------
__global__ void conv3x3_k(const float* __restrict__ in, const float* __restrict__ w,
                          float* __restrict__ out, int Cin, int do_relu)
{
    extern __shared__ float s_in[];  // Cin*144
    int img = blockIdx.x;
    int tid = threadIdx.x;
    const float* inb = in + (size_t)img * Cin * HW;
    for (int idx = tid; idx < Cin * 144; idx += 256) {
        int c = idx / 144, pos = idx % 144;
        int y = pos / 12 - 1, x = pos % 12 - 1;
        float v = 0.0f;
        if (y >= 0 && y < 10 && x >= 0 && x < 10) v = inb[c * HW + y * 10 + x];
        s_in[idx] = v;
    }
    __syncthreads();

    int oc = blockIdx.y * 16 + (tid >> 4);
    int lane = tid & 15;
    float acc[7];
    int base[7];
#pragma unroll
    for (int t = 0; t < 7; t++) {
        acc[t] = 0.0f;
        int p = lane + 16 * t;
        if (p > 99) p = 99;
        int y = p / 10, x = p % 10;
        base[t] = y * 12 + x;
    }
    const float* wb = w + (size_t)oc * Cin * 9;
    for (int c = 0; c < Cin; c++) {
        const float* sc = s_in + c * 144;
#pragma unroll
        for (int kk = 0; kk < 9; kk++) {
            float wv = wb[c * 9 + kk];
            int off = (kk / 3) * 12 + (kk % 3);
#pragma unroll
            for (int t = 0; t < 7; t++)
                acc[t] += sc[base[t] + off] * wv;
        }
    }
    float* ob = out + (size_t)img * T_CH * HW + oc * HW;
#pragma unroll
    for (int t = 0; t < 7; t++) {
        int p = lane + 16 * t;
        if (p < HW) {
            float v = acc[t];
            if (do_relu) v = fmaxf(v, 0.0f);
            ob[p] = v;
        }
    }
}

// ---------------------------------------------------------------------------
// Final: out[b][c][t] = (1/100) * sum_p sigmoid(T4[b][t][p]) * F[b][c][p]
// ---------------------------------------------------------------------------
__global__ void rfm_out_k(const float* __restrict__ T4, const float* __restrict__ F,
                          float* __restrict__ out)
{
    int img = blockIdx.x;
    __shared__ float sig[HW * T_CH];  // [p][t]
    int tid = threadIdx.x;
    for (int idx = tid; idx < T_CH * HW; idx += 256) {
        int t = idx / HW, p = idx % HW;
        float v = T4[(size_t)img * T_CH * HW + idx];
        sig[p * T_CH + t] = 1.0f / (1.0f + __expf(-v));
    }
    __syncthreads();
    float* ob = out + (size_t)img * 4096;
    const float* fb = F + (size_t)img * C_DIM * HW;
    for (int o = tid; o < C_DIM * T_CH; o += 256) {
        int c = o >> 5, t = o & 31;
        float s = 0.0f;
        for (int p = 0; p < HW; p++)
            s += fb[c * HW + p] * sig[p * T_CH + t];
        ob[c * T_CH + t] = s * (1.0f / 100.0f);
    }
}

// ---------------------------------------------------------------------------
// Host launcher
// ---------------------------------------------------------------------------
extern "C" void kernel_launch(void* const* d_in, const int* in_sizes, int n_in,
                              void* d_out, int out_size)
{
    const float* support = (const float*)d_in[0];
    const float* query   = (const float*)d_in[1];
    const float* task    = (const float*)d_in[2];
    const float* ln1_g   = (const float*)d_in[3];
    const float* ln1_b   = (const float*)d_in[4];
    const float* qkv_w   = (const float*)d_in[5];
    const float* qkv_b   = (const float*)d_in[6];
    const float* out_w   = (const float*)d_in[7];
    const float* out_b   = (const float*)d_in[8];
    const float* ln2_g   = (const float*)d_in[9];
    const float* ln2_b   = (const float*)d_in[10];
    const float* mlp_w1  = (const float*)d_in[11];
    const float* mlp_b1  = (const float*)d_in[12];
    const float* mlp_w2  = (const float*)d_in[13];
    const float* mlp_b2  = (const float*)d_in[14];
    const float* rln_g   = (const float*)d_in[15];
    const float* rln_b   = (const float*)d_in[16];
    const float* conv1   = (const float*)d_in[17];
    const float* conv2   = (const float*)d_in[18];
    const float* conv3   = (const float*)d_in[19];
    const float* conv4   = (const float*)d_in[20];

    float *X, *H, *QKV, *O, *G, *PART, *ML, *FUSED, *LNT, *T1, *T2;
    cudaGetSymbolAddress((void**)&X, g_X);
    cudaGetSymbolAddress((void**)&H, g_H);
    cudaGetSymbolAddress((void**)&QKV, g_QKV);
    cudaGetSymbolAddress((void**)&O, g_O);
    cudaGetSymbolAddress((void**)&G, g_G);
    cudaGetSymbolAddress((void**)&PART, g_PART);
    cudaGetSymbolAddress((void**)&ML, g_ML);
    cudaGetSymbolAddress((void**)&FUSED, g_FUSED);
    cudaGetSymbolAddress((void**)&LNT, g_LNT);
    cudaGetSymbolAddress((void**)&T1, g_T1);
    cudaGetSymbolAddress((void**)&T2, g_T2);

    cudaFuncSetAttribute(conv3x3_k, cudaFuncAttributeMaxDynamicSharedMemorySize,
                         C_DIM * 144 * sizeof(float));

    // Build sequence
    build_x_k<<<(L_SEQ * C_DIM + 255) / 256, 256>>>(task, support, X);

    // Transformer (2 layers)
    for (int i = 0; i < 2; i++) {
        ln_rows_k<<<L_SEQ, 128>>>(X, ln1_g + i * C_DIM, ln1_b + i * C_DIM, H, 1e-5f);
        gemm_epi_k<<<dim3(6, 40), 256>>>(H, qkv_w + (size_t)i * C_DIM * 384,
                                         qkv_b + i * 384, nullptr, QKV,
                                         L_SEQ, 384, C_DIM, 0);
        attn_partial_k<<<dim3(10, HEADS_N, KSPLIT), 128>>>(QKV, PART, ML);
        attn_merge_k<<<(HEADS_N * L_SEQ + 127) / 128, 128>>>(PART, ML, O);
        gemm_epi_k<<<dim3(2, 40), 256>>>(O, out_w + (size_t)i * C_DIM * C_DIM,
                                         out_b + i * C_DIM, X, X,
                                         L_SEQ, C_DIM, C_DIM, 1);
        ln_rows_k<<<L_SEQ, 128>>>(X, ln2_g + i * C_DIM, ln2_b + i * C_DIM, H, 1e-5f);
        gemm_epi_k<<<dim3(8, 40), 256>>>(H, mlp_w1 + (size_t)i * C_DIM * MLP_DIM,
                                         mlp_b1 + i * MLP_DIM, nullptr, G,
                                         L_SEQ, MLP_DIM, C_DIM, 2);
        gemm_epi_k<<<dim3(2, 40), 256>>>(G, mlp_w2 + (size_t)i * MLP_DIM * C_DIM,
                                         mlp_b2 + i * C_DIM, X, X,
                                         L_SEQ, C_DIM, MLP_DIM, 1);
    }

    // Region + fuse
    region_fuse_k<<<N_IMG, 128>>>(support, query, X, FUSED);
    ln_chan_k<<<N_IMG, 128>>>(FUSED, rln_g, rln_b, LNT);

    // RFM convs (oc split across grid.y)
    conv3x3_k<<<dim3(N_IMG, 2), 256, C_DIM * 144 * sizeof(float)>>>(LNT, conv1, T1, C_DIM, 1);
    conv3x3_k<<<dim3(N_IMG, 2), 256, T_CH * 144 * sizeof(float)>>>(T1, conv2, T2, T_CH, 1);
    conv3x3_k<<<dim3(N_IMG, 2), 256, T_CH * 144 * sizeof(float)>>>(T2, conv3, T1, T_CH, 1);
    conv3x3_k<<<dim3(N_IMG, 2), 256, T_CH * 144 * sizeof(float)>>>(T1, conv4, T2, T_CH, 0);

    // Weighted pooling -> output
    rfm_out_k<<<N_IMG, 256>>>(T2, FUSED, (float*)d_out);
}